// round 12
// baseline (speedup 1.0000x reference)
#include <cuda_runtime.h>
#include <cuda_fp16.h>
#include <cstdint>
#include <math.h>

// Problem constants
#define NT      8192      // tokens = B*S
#define DD      512       // dim_model
#define FF      2048      // dim_feedforward
#define EE      8         // experts
#define MAXTOK  8192      // per-expert worst case

// ---------------- scratch (device globals; no allocations allowed) ----------
__device__ __align__(16) int    g_cnt[EE];
__device__ __align__(16) int    g_pos[NT * 2];           // e*MAXTOK+slot per (token,k)
__device__ __align__(16) int    g_tok[EE * MAXTOK];      // slot -> token id
__device__ __align__(16) float  g_wtok[EE * MAXTOK];     // slot -> gate weight
__device__ __align__(16) __half g_xg[(size_t)EE * MAXTOK * DD];      // packed A rows (fp16)
__device__ __align__(16) __half g_w1h[(size_t)EE * DD * FF];         // w1 fp16 [E][D][F]
__device__ __align__(16) __half g_w2h[(size_t)EE * FF * DD];         // w2 fp16 [E][F][D]
__device__ __align__(16) __half g_hidden[(size_t)EE * MAXTOK * FF];  // hidden (fp16)

// ---------------- helpers ----------------------------------------------------
__device__ __forceinline__ uint32_t smem_to_u32(const void* p) {
    uint32_t a;
    asm("{ .reg .u64 t; cvta.to.shared.u64 t, %1; cvt.u32.u64 %0, t; }"
        : "=r"(a) : "l"(p));
    return a;
}

// ---------------- counters reset --------------------------------------------
__global__ void zero_cnt_kernel() {
    if (threadIdx.x < EE) g_cnt[threadIdx.x] = 0;
}

// ---------------- zero output (d_out poisoned; epilogue atomics need 0) -----
__global__ void zero_out_kernel(float4* __restrict__ out) {
    out[blockIdx.x * blockDim.x + threadIdx.x] = make_float4(0.f, 0.f, 0.f, 0.f);
}

// ---------------- fp32 -> fp16 weight convert (globals referenced in-device!)
template <int MODE>
__global__ void conv_kernel(const float* __restrict__ src) {
    __half2* __restrict__ dst = (__half2*)((MODE == 0) ? g_w1h : g_w2h);
    const int i = blockIdx.x * blockDim.x + threadIdx.x;
    const float4 v = ((const float4*)src)[i];
    dst[2 * i]     = __floats2half2_rn(v.x, v.y);
    dst[2 * i + 1] = __floats2half2_rn(v.z, v.w);
}

// ---------------- router: one warp per token --------------------------------
__global__ void router_kernel(const float* __restrict__ x,
                              const float* __restrict__ rw,
                              const float* __restrict__ rb) {
    __shared__ float srw[DD * EE];
    const int tid = threadIdx.x;
    for (int i = tid; i < DD * EE; i += blockDim.x) srw[i] = rw[i];
    __syncthreads();

    const int warp = tid >> 5, lane = tid & 31;
    const int t = blockIdx.x * (blockDim.x >> 5) + warp;
    if (t >= NT) return;

    const float* __restrict__ xr = x + (size_t)t * DD;
    float acc[EE];
#pragma unroll
    for (int e = 0; e < EE; e++) acc[e] = 0.f;
    for (int d = lane; d < DD; d += 32) {
        const float xv = xr[d];
#pragma unroll
        for (int e = 0; e < EE; e++) acc[e] = fmaf(xv, srw[d * EE + e], acc[e]);
    }
#pragma unroll
    for (int e = 0; e < EE; e++)
#pragma unroll
        for (int o = 16; o > 0; o >>= 1)
            acc[e] += __shfl_xor_sync(0xffffffffu, acc[e], o);

    if (lane == 0) {
#pragma unroll
        for (int e = 0; e < EE; e++) acc[e] += rb[e];
        int e0 = 0;
#pragma unroll
        for (int e = 1; e < EE; e++) if (acc[e] > acc[e0]) e0 = e;
        int e1 = -1;
#pragma unroll
        for (int e = 0; e < EE; e++) {
            if (e == e0) continue;
            if (e1 < 0 || acc[e] > acc[e1]) e1 = e;
        }
        const float r = expf(acc[e1] - acc[e0]);
        const float w0 = 1.f / (1.f + r);
        const float w1 = r / (1.f + r);
        const int s0 = atomicAdd(&g_cnt[e0], 1);
        const int s1 = atomicAdd(&g_cnt[e1], 1);
        g_pos[2 * t]     = e0 * MAXTOK + s0;
        g_pos[2 * t + 1] = e1 * MAXTOK + s1;
        g_tok [e0 * MAXTOK + s0] = t;  g_wtok[e0 * MAXTOK + s0] = w0;
        g_tok [e1 * MAXTOK + s1] = t;  g_wtok[e1 * MAXTOK + s1] = w1;
    }
}

// ---------------- pack: gather token rows, convert to fp16 -------------------
__global__ void pack_kernel(const float* __restrict__ x) {
    const int row = blockIdx.x;            // 0 .. 2*NT-1
    const int t = row >> 1, k = row & 1;
    const int pos = g_pos[2 * t + k];
    const float4* __restrict__ src = (const float4*)(x + (size_t)t * DD);
    __half2* __restrict__ dst = (__half2*)(g_xg + (size_t)pos * DD);
    const float4 v = src[threadIdx.x];     // 128 threads x 4 floats
    dst[2 * threadIdx.x]     = __floats2half2_rn(v.x, v.y);
    dst[2 * threadIdx.x + 1] = __floats2half2_rn(v.z, v.w);
}

// ---------------- fp16 mma.sync GEMM -----------------------------------------
// C[e][m][n] = A[e][m][:] . B[e][:][n]   (B natural [K][N] layout)
// CTA 128x128, BK=64, 256 threads = 8 warps (2m x 4n), warp tile 64x32,
// ldmatrix (A) + ldmatrix.trans (B), mma.sync.m16n8k16, 2 CTA/SM.
// MODE 0: A=g_xg,     B=g_w1h, out: g_hidden (relu+bias, fp16)
// MODE 1: A=g_hidden, B=g_w2h, out: atomicAdd into d_out with gate weights
#define BKH    64                  // K elements per tile
#define S32A   36                  // A smem row stride (words): 32 payload + 4 pad
#define S32B   68                  // B smem row stride (words): 64 payload + 4 pad
#define BUFA32 (128 * S32A)        // 4608 words
#define BUFB32 (64 * S32B)         // 4352 words

template <int MODE>
__global__ void __launch_bounds__(256, 2)
moe_gemm_kernel(const float* __restrict__ bias, float* __restrict__ out) {
    constexpr int K    = (MODE == 0) ? DD : FF;
    constexpr int NTOT = (MODE == 0) ? FF : DD;
    const __half* __restrict__ A = (MODE == 0) ? g_xg  : g_hidden;
    const __half* __restrict__ W = (MODE == 0) ? g_w1h : g_w2h;

    const int e   = blockIdx.z;
    const int n_e = g_cnt[e];
    const int m0  = blockIdx.y * 128;
    if (m0 >= n_e) return;
    const int n0  = blockIdx.x * 128;

    extern __shared__ uint32_t sm32[];
    const uint32_t sA = smem_to_u32(sm32);                  // A: 2 stages
    const uint32_t sB = sA + 2u * BUFA32 * 4u;              // B: 2 stages

    const int tid  = threadIdx.x;
    const int wid  = tid >> 5, lane = tid & 31;
    const int qid  = lane >> 2, tq = lane & 3;
    const int wm   = (wid >> 2) * 64;     // warp m-base
    const int wn   = (wid & 3) * 32;      // warp n-base

    const __half* __restrict__ Ab = A + ((size_t)e * MAXTOK + m0) * K;
    const __half* __restrict__ Bb = W + (size_t)e * K * NTOT + n0;

    // A loader mapping: 32 rows/pass x 16B granules
    const int arow = tid >> 3;   // 0..31
    const int ag   = tid & 7;
    // B loader mapping: 64 rows x 4 chunks of 16B
    const int brow = tid >> 2;   // 0..63
    const int bc   = tid & 3;

    // ---- ldmatrix per-lane offsets (bytes within one stage buffer)
    const int grp = lane >> 3, lr = lane & 7;
    uint32_t aOff[4], bOff[2];
#pragma unroll
    for (int i = 0; i < 4; i++) {
        const int row = wm + i * 16 + lr + ((grp & 1) ? 8 : 0);
        const int col = (grp & 2) ? 4 : 0;
        aOff[i] = (uint32_t)(row * S32A + col) * 4u;
    }
    // B tiles (trans): grp 0..3 -> (kLo,nLo)(kHi,nLo)(kLo,nHi)(kHi,nHi)
#pragma unroll
    for (int jp = 0; jp < 2; jp++) {
        const int krow = 8 * (grp & 1) + lr;
        const int ncol = wn + 16 * jp + 8 * (grp >> 1);     // halves
        bOff[jp] = (uint32_t)(krow * S32B + (ncol >> 1)) * 4u;
    }

    float acc[4][4][4];
#pragma unroll
    for (int i = 0; i < 4; i++)
#pragma unroll
        for (int j = 0; j < 4; j++)
#pragma unroll
            for (int c = 0; c < 4; c++) acc[i][j][c] = 0.f;

    // ---- tile loader
    auto load_tile = [&](int kt, int buf) {
        const uint32_t ab = sA + (uint32_t)buf * BUFA32 * 4u;
        const uint32_t bb = sB + (uint32_t)buf * BUFB32 * 4u;
        const int k0 = kt * BKH;
#pragma unroll
        for (int i = 0; i < 4; i++) {
            const int row = arow + 32 * i;
            const uint32_t so = (uint32_t)(row * S32A + ag * 4) * 4u;
            asm volatile("cp.async.cg.shared.global [%0], [%1], 16;"
                         :: "r"(ab + so), "l"(Ab + (size_t)row * K + k0 + ag * 8) : "memory");
        }
#pragma unroll
        for (int i = 0; i < 4; i++) {
            const int chunk = bc + 4 * i;                    // 0..15
            const uint32_t so = (uint32_t)(brow * S32B + chunk * 4) * 4u;
            asm volatile("cp.async.cg.shared.global [%0], [%1], 16;"
                         :: "r"(bb + so), "l"(Bb + (size_t)(k0 + brow) * NTOT + chunk * 8) : "memory");
        }
        asm volatile("cp.async.commit_group;" ::: "memory");
    };

    constexpr int KT = K / BKH;
    load_tile(0, 0);

    for (int kt = 0; kt < KT; kt++) {
        if (kt + 1 < KT) {
            load_tile(kt + 1, (kt + 1) & 1);
            asm volatile("cp.async.wait_group 1;" ::: "memory");
        } else {
            asm volatile("cp.async.wait_group 0;" ::: "memory");
        }
        __syncthreads();

        const uint32_t aBase = sA + (uint32_t)(kt & 1) * BUFA32 * 4u;
        const uint32_t bBase = sB + (uint32_t)(kt & 1) * BUFB32 * 4u;

#pragma unroll
        for (int ks = 0; ks < 4; ks++) {                    // 4 x k16 per tile
            const uint32_t kaddA = (uint32_t)ks * 32u;      // 8 words
            const uint32_t kaddB = (uint32_t)(ks * 16 * S32B) * 4u;  // 16 rows
            uint32_t af[4][4], bf[4][2];
#pragma unroll
            for (int i = 0; i < 4; i++)
                asm volatile(
                    "ldmatrix.sync.aligned.m8n8.x4.shared.b16 {%0,%1,%2,%3}, [%4];"
                    : "=r"(af[i][0]), "=r"(af[i][1]), "=r"(af[i][2]), "=r"(af[i][3])
                    : "r"(aBase + aOff[i] + kaddA));
#pragma unroll
            for (int jp = 0; jp < 2; jp++)
                asm volatile(
                    "ldmatrix.sync.aligned.m8n8.x4.trans.shared.b16 {%0,%1,%2,%3}, [%4];"
                    : "=r"(bf[2 * jp][0]), "=r"(bf[2 * jp][1]),
                      "=r"(bf[2 * jp + 1][0]), "=r"(bf[2 * jp + 1][1])
                    : "r"(bBase + bOff[jp] + kaddB));
#pragma unroll
            for (int i = 0; i < 4; i++)
#pragma unroll
                for (int j = 0; j < 4; j++)
                    asm volatile(
                        "mma.sync.aligned.m16n8k16.row.col.f32.f16.f16.f32 "
                        "{%0,%1,%2,%3}, {%4,%5,%6,%7}, {%8,%9}, {%0,%1,%2,%3};"
                        : "+f"(acc[i][j][0]), "+f"(acc[i][j][1]),
                          "+f"(acc[i][j][2]), "+f"(acc[i][j][3])
                        : "r"(af[i][0]), "r"(af[i][1]), "r"(af[i][2]), "r"(af[i][3]),
                          "r"(bf[j][0]), "r"(bf[j][1]));
        }
        __syncthreads();
    }

    // ---- epilogue
    const float* __restrict__ bb = bias + (size_t)e * NTOT + n0;

    if (MODE == 0) {
        // bias + relu, store fp16 hidden
        __half* __restrict__ Cb = g_hidden + ((size_t)e * MAXTOK + m0) * NTOT + n0;
#pragma unroll
        for (int j = 0; j < 4; j++) {
            const int cn = wn + j * 8 + 2 * tq;
            const float b0 = bb[cn], b1 = bb[cn + 1];
#pragma unroll
            for (int i = 0; i < 4; i++) {
                const int r0 = wm + i * 16 + qid;
                const int r1 = r0 + 8;
                const __half2 v0 = __floats2half2_rn(fmaxf(acc[i][j][0] + b0, 0.f),
                                                     fmaxf(acc[i][j][1] + b1, 0.f));
                const __half2 v1 = __floats2half2_rn(fmaxf(acc[i][j][2] + b0, 0.f),
                                                     fmaxf(acc[i][j][3] + b1, 0.f));
                if (m0 + r0 < n_e) *(__half2*)(Cb + (size_t)r0 * NTOT + cn) = v0;
                if (m0 + r1 < n_e) *(__half2*)(Cb + (size_t)r1 * NTOT + cn) = v1;
            }
        }
    } else {
        // bias, then scatter w*(acc+b) into out[token] via atomics
        const int*   __restrict__ tokp = g_tok  + (size_t)e * MAXTOK + m0;
        const float* __restrict__ wp   = g_wtok + (size_t)e * MAXTOK + m0;
#pragma unroll
        for (int j = 0; j < 4; j++) {
            const int cn = wn + j * 8 + 2 * tq;
            const float b0 = bb[cn], b1 = bb[cn + 1];
#pragma unroll
            for (int i = 0; i < 4; i++) {
                const int r0 = wm + i * 16 + qid;
                const int r1 = r0 + 8;
                if (m0 + r0 < n_e) {
                    const float w = wp[r0];
                    float* o = out + (size_t)tokp[r0] * DD + n0 + cn;
                    atomicAdd(o,     w * (acc[i][j][0] + b0));
                    atomicAdd(o + 1, w * (acc[i][j][1] + b1));
                }
                if (m0 + r1 < n_e) {
                    const float w = wp[r1];
                    float* o = out + (size_t)tokp[r1] * DD + n0 + cn;
                    atomicAdd(o,     w * (acc[i][j][2] + b0));
                    atomicAdd(o + 1, w * (acc[i][j][3] + b1));
                }
            }
        }
    }
}

// ---------------- launch -----------------------------------------------------
#define SMEM_BYTES ((2u * BUFA32 + 2u * BUFB32) * 4u)   // 71680 B

extern "C" void kernel_launch(void* const* d_in, const int* in_sizes, int n_in,
                              void* d_out, int out_size) {
    const float* x   = (const float*)d_in[0];
    const float* rw  = (const float*)d_in[1];
    const float* rb  = (const float*)d_in[2];
    const float* w1  = (const float*)d_in[3];
    const float* b1  = (const float*)d_in[4];
    const float* w2  = (const float*)d_in[5];
    const float* b2  = (const float*)d_in[6];
    float* out = (float*)d_out;

    cudaFuncSetAttribute(moe_gemm_kernel<0>,
                         cudaFuncAttributeMaxDynamicSharedMemorySize, SMEM_BYTES);
    cudaFuncSetAttribute(moe_gemm_kernel<1>,
                         cudaFuncAttributeMaxDynamicSharedMemorySize, SMEM_BYTES);

    zero_cnt_kernel<<<1, 32>>>();
    zero_out_kernel<<<(NT * DD / 4) / 256, 256>>>((float4*)out);
    router_kernel<<<NT / 8, 256>>>(x, rw, rb);
    pack_kernel<<<NT * 2, 128>>>(x);

    // fp32 -> fp16 weight converts (natural layout, no transpose)
    conv_kernel<0><<<(EE * DD * FF / 4) / 256, 256>>>(w1);
    conv_kernel<1><<<(EE * FF * DD / 4) / 256, 256>>>(w2);

    // GEMM1: hidden = relu(xg @ w1 + b1)   (K = DD, N = FF)
    moe_gemm_kernel<0><<<dim3(FF / 128, MAXTOK / 128, EE), 256, SMEM_BYTES>>>(b1, nullptr);
    // GEMM2: out += gate * (hidden @ w2 + b2)  (K = FF, N = DD, fused combine)
    moe_gemm_kernel<1><<<dim3(DD / 128, MAXTOK / 128, EE), 256, SMEM_BYTES>>>(b2, out);
}

// round 15
// speedup vs baseline: 1.0046x; 1.0046x over previous
#include <cuda_runtime.h>
#include <cuda_fp16.h>
#include <cstdint>
#include <math.h>

// Problem constants
#define NT      8192      // tokens = B*S
#define DD      512       // dim_model
#define FF      2048      // dim_feedforward
#define EE      8         // experts
#define MAXTOK  8192      // per-expert worst case

// ---------------- scratch (device globals; no allocations allowed) ----------
__device__ __align__(16) int    g_cnt[EE];
__device__ __align__(16) int    g_pos[NT * 2];           // e*MAXTOK+slot per (token,k)
__device__ __align__(16) float  g_wt [NT * 2];           // renormalized gate weights
__device__ __align__(16) __half g_xg[(size_t)EE * MAXTOK * DD];      // packed A rows (fp16)
__device__ __align__(16) __half g_w1h[(size_t)EE * DD * FF];         // w1 fp16 [E][D][F]
__device__ __align__(16) __half g_w2h[(size_t)EE * FF * DD];         // w2 fp16 [E][F][D]
__device__ __align__(16) __half g_hidden[(size_t)EE * MAXTOK * FF];  // hidden (fp16)
__device__ __align__(16) float  g_y[(size_t)EE * MAXTOK * DD];       // expert outputs (fp32)

// ---------------- helpers ----------------------------------------------------
__device__ __forceinline__ uint32_t smem_to_u32(const void* p) {
    uint32_t a;
    asm("{ .reg .u64 t; cvta.to.shared.u64 t, %1; cvt.u32.u64 %0, t; }"
        : "=r"(a) : "l"(p));
    return a;
}

// ---------------- counters reset --------------------------------------------
__global__ void zero_cnt_kernel() {
    if (threadIdx.x < EE) g_cnt[threadIdx.x] = 0;
}

// ---------------- fp32 -> fp16 weight convert (globals referenced in-device!)
template <int MODE>
__global__ void conv_kernel(const float* __restrict__ src) {
    __half2* __restrict__ dst = (__half2*)((MODE == 0) ? g_w1h : g_w2h);
    const int i = blockIdx.x * blockDim.x + threadIdx.x;
    const float4 v = ((const float4*)src)[i];
    dst[2 * i]     = __floats2half2_rn(v.x, v.y);
    dst[2 * i + 1] = __floats2half2_rn(v.z, v.w);
}

// ---------------- router: one warp per token --------------------------------
__global__ void router_kernel(const float* __restrict__ x,
                              const float* __restrict__ rw,
                              const float* __restrict__ rb) {
    __shared__ float srw[DD * EE];
    const int tid = threadIdx.x;
    for (int i = tid; i < DD * EE; i += blockDim.x) srw[i] = rw[i];
    __syncthreads();

    const int warp = tid >> 5, lane = tid & 31;
    const int t = blockIdx.x * (blockDim.x >> 5) + warp;
    if (t >= NT) return;

    const float* __restrict__ xr = x + (size_t)t * DD;
    float acc[EE];
#pragma unroll
    for (int e = 0; e < EE; e++) acc[e] = 0.f;
    for (int d = lane; d < DD; d += 32) {
        const float xv = xr[d];
#pragma unroll
        for (int e = 0; e < EE; e++) acc[e] = fmaf(xv, srw[d * EE + e], acc[e]);
    }
#pragma unroll
    for (int e = 0; e < EE; e++)
#pragma unroll
        for (int o = 16; o > 0; o >>= 1)
            acc[e] += __shfl_xor_sync(0xffffffffu, acc[e], o);

    if (lane == 0) {
#pragma unroll
        for (int e = 0; e < EE; e++) acc[e] += rb[e];
        int e0 = 0;
#pragma unroll
        for (int e = 1; e < EE; e++) if (acc[e] > acc[e0]) e0 = e;
        int e1 = -1;
#pragma unroll
        for (int e = 0; e < EE; e++) {
            if (e == e0) continue;
            if (e1 < 0 || acc[e] > acc[e1]) e1 = e;
        }
        const float r = expf(acc[e1] - acc[e0]);
        const float w0 = 1.f / (1.f + r);
        const float w1 = r / (1.f + r);
        const int s0 = atomicAdd(&g_cnt[e0], 1);
        const int s1 = atomicAdd(&g_cnt[e1], 1);
        g_pos[2 * t]     = e0 * MAXTOK + s0;
        g_pos[2 * t + 1] = e1 * MAXTOK + s1;
        g_wt [2 * t]     = w0;
        g_wt [2 * t + 1] = w1;
    }
}

// ---------------- pack: gather token rows, convert to fp16 -------------------
__global__ void pack_kernel(const float* __restrict__ x) {
    const int row = blockIdx.x;            // 0 .. 2*NT-1
    const int t = row >> 1, k = row & 1;
    const int pos = g_pos[2 * t + k];
    const float4* __restrict__ src = (const float4*)(x + (size_t)t * DD);
    __half2* __restrict__ dst = (__half2*)(g_xg + (size_t)pos * DD);
    const float4 v = src[threadIdx.x];     // 128 threads x 4 floats
    dst[2 * threadIdx.x]     = __floats2half2_rn(v.x, v.y);
    dst[2 * threadIdx.x + 1] = __floats2half2_rn(v.z, v.w);
}

// ---------------- fp16 mma.sync GEMM -----------------------------------------
// C[e][m][n] = A[e][m][:] . B[e][:][n]   (B natural [K][N] layout)
// CTA 128x128, BK=64, 256 threads = 8 warps (2m x 4n), warp tile 64x32,
// ldmatrix (A) + ldmatrix.trans (B), mma.sync.m16n8k16, 2 CTA/SM.
// MODE 0: A=g_xg,     B=g_w1h, out: g_hidden (relu+bias, fp16)
// MODE 1: A=g_hidden, B=g_w2h, out: g_y (bias, fp32)
#define BKH    64                  // K elements per tile
#define S32A   36                  // A smem row stride (words): 32 payload + 4 pad
#define S32B   68                  // B smem row stride (words): 64 payload + 4 pad
#define BUFA32 (128 * S32A)        // 4608 words
#define BUFB32 (64 * S32B)         // 4352 words

template <int MODE>
__global__ void __launch_bounds__(256, 2)
moe_gemm_kernel(const float* __restrict__ bias) {
    constexpr int K    = (MODE == 0) ? DD : FF;
    constexpr int NTOT = (MODE == 0) ? FF : DD;
    const __half* __restrict__ A = (MODE == 0) ? g_xg  : g_hidden;
    const __half* __restrict__ W = (MODE == 0) ? g_w1h : g_w2h;

    const int e   = blockIdx.z;
    const int n_e = g_cnt[e];
    const int m0  = blockIdx.y * 128;
    if (m0 >= n_e) return;
    const int n0  = blockIdx.x * 128;

    extern __shared__ uint32_t sm32[];
    const uint32_t sA = smem_to_u32(sm32);                  // A: 2 stages
    const uint32_t sB = sA + 2u * BUFA32 * 4u;              // B: 2 stages

    const int tid  = threadIdx.x;
    const int wid  = tid >> 5, lane = tid & 31;
    const int qid  = lane >> 2, tq = lane & 3;
    const int wm   = (wid >> 2) * 64;     // warp m-base
    const int wn   = (wid & 3) * 32;      // warp n-base

    const __half* __restrict__ Ab = A + ((size_t)e * MAXTOK + m0) * K;
    const __half* __restrict__ Bb = W + (size_t)e * K * NTOT + n0;

    // A loader mapping: 32 rows/pass x 16B granules
    const int arow = tid >> 3;   // 0..31
    const int ag   = tid & 7;
    // B loader mapping: 64 rows x 4 chunks of 16B
    const int brow = tid >> 2;   // 0..63
    const int bc   = tid & 3;

    // ---- ldmatrix per-lane offsets (bytes within one stage buffer)
    const int grp = lane >> 3, lr = lane & 7;
    uint32_t aOff[4], bOff[2];
#pragma unroll
    for (int i = 0; i < 4; i++) {
        const int row = wm + i * 16 + lr + ((grp & 1) ? 8 : 0);
        const int col = (grp & 2) ? 4 : 0;
        aOff[i] = (uint32_t)(row * S32A + col) * 4u;
    }
    // B tiles (trans): grp 0..3 -> (kLo,nLo)(kHi,nLo)(kLo,nHi)(kHi,nHi)
#pragma unroll
    for (int jp = 0; jp < 2; jp++) {
        const int krow = 8 * (grp & 1) + lr;
        const int ncol = wn + 16 * jp + 8 * (grp >> 1);     // halves
        bOff[jp] = (uint32_t)(krow * S32B + (ncol >> 1)) * 4u;
    }

    float acc[4][4][4];
#pragma unroll
    for (int i = 0; i < 4; i++)
#pragma unroll
        for (int j = 0; j < 4; j++)
#pragma unroll
            for (int c = 0; c < 4; c++) acc[i][j][c] = 0.f;

    // ---- tile loader
    auto load_tile = [&](int kt, int buf) {
        const uint32_t ab = sA + (uint32_t)buf * BUFA32 * 4u;
        const uint32_t bb = sB + (uint32_t)buf * BUFB32 * 4u;
        const int k0 = kt * BKH;
#pragma unroll
        for (int i = 0; i < 4; i++) {
            const int row = arow + 32 * i;
            const uint32_t so = (uint32_t)(row * S32A + ag * 4) * 4u;
            asm volatile("cp.async.cg.shared.global [%0], [%1], 16;"
                         :: "r"(ab + so), "l"(Ab + (size_t)row * K + k0 + ag * 8) : "memory");
        }
#pragma unroll
        for (int i = 0; i < 4; i++) {
            const int chunk = bc + 4 * i;                    // 0..15
            const uint32_t so = (uint32_t)(brow * S32B + chunk * 4) * 4u;
            asm volatile("cp.async.cg.shared.global [%0], [%1], 16;"
                         :: "r"(bb + so), "l"(Bb + (size_t)(k0 + brow) * NTOT + chunk * 8) : "memory");
        }
        asm volatile("cp.async.commit_group;" ::: "memory");
    };

    constexpr int KT = K / BKH;
    load_tile(0, 0);

    for (int kt = 0; kt < KT; kt++) {
        if (kt + 1 < KT) {
            load_tile(kt + 1, (kt + 1) & 1);
            asm volatile("cp.async.wait_group 1;" ::: "memory");
        } else {
            asm volatile("cp.async.wait_group 0;" ::: "memory");
        }
        __syncthreads();

        const uint32_t aBase = sA + (uint32_t)(kt & 1) * BUFA32 * 4u;
        const uint32_t bBase = sB + (uint32_t)(kt & 1) * BUFB32 * 4u;

#pragma unroll
        for (int ks = 0; ks < 4; ks++) {                    // 4 x k16 per tile
            const uint32_t kaddA = (uint32_t)ks * 32u;      // 8 words
            const uint32_t kaddB = (uint32_t)(ks * 16 * S32B) * 4u;  // 16 rows
            uint32_t af[4][4], bf[4][2];
#pragma unroll
            for (int i = 0; i < 4; i++)
                asm volatile(
                    "ldmatrix.sync.aligned.m8n8.x4.shared.b16 {%0,%1,%2,%3}, [%4];"
                    : "=r"(af[i][0]), "=r"(af[i][1]), "=r"(af[i][2]), "=r"(af[i][3])
                    : "r"(aBase + aOff[i] + kaddA));
#pragma unroll
            for (int jp = 0; jp < 2; jp++)
                asm volatile(
                    "ldmatrix.sync.aligned.m8n8.x4.trans.shared.b16 {%0,%1,%2,%3}, [%4];"
                    : "=r"(bf[2 * jp][0]), "=r"(bf[2 * jp][1]),
                      "=r"(bf[2 * jp + 1][0]), "=r"(bf[2 * jp + 1][1])
                    : "r"(bBase + bOff[jp] + kaddB));
#pragma unroll
            for (int i = 0; i < 4; i++)
#pragma unroll
                for (int j = 0; j < 4; j++)
                    asm volatile(
                        "mma.sync.aligned.m16n8k16.row.col.f32.f16.f16.f32 "
                        "{%0,%1,%2,%3}, {%4,%5,%6,%7}, {%8,%9}, {%0,%1,%2,%3};"
                        : "+f"(acc[i][j][0]), "+f"(acc[i][j][1]),
                          "+f"(acc[i][j][2]), "+f"(acc[i][j][3])
                        : "r"(af[i][0]), "r"(af[i][1]), "r"(af[i][2]), "r"(af[i][3]),
                          "r"(bf[j][0]), "r"(bf[j][1]));
        }
        __syncthreads();
    }

    // ---- epilogue
    const float* __restrict__ bb = bias + (size_t)e * NTOT + n0;

    if (MODE == 0) {
        // bias + relu, store fp16 hidden
        __half* __restrict__ Cb = g_hidden + ((size_t)e * MAXTOK + m0) * NTOT + n0;
#pragma unroll
        for (int j = 0; j < 4; j++) {
            const int cn = wn + j * 8 + 2 * tq;
            const float b0 = bb[cn], b1 = bb[cn + 1];
#pragma unroll
            for (int i = 0; i < 4; i++) {
                const int r0 = wm + i * 16 + qid;
                const int r1 = r0 + 8;
                const __half2 v0 = __floats2half2_rn(fmaxf(acc[i][j][0] + b0, 0.f),
                                                     fmaxf(acc[i][j][1] + b1, 0.f));
                const __half2 v1 = __floats2half2_rn(fmaxf(acc[i][j][2] + b0, 0.f),
                                                     fmaxf(acc[i][j][3] + b1, 0.f));
                if (m0 + r0 < n_e) *(__half2*)(Cb + (size_t)r0 * NTOT + cn) = v0;
                if (m0 + r1 < n_e) *(__half2*)(Cb + (size_t)r1 * NTOT + cn) = v1;
            }
        }
    } else {
        // bias, store fp32 y (coalesced float2)
        float* __restrict__ Cb = g_y + ((size_t)e * MAXTOK + m0) * NTOT + n0;
#pragma unroll
        for (int j = 0; j < 4; j++) {
            const int cn = wn + j * 8 + 2 * tq;
            const float b0 = bb[cn], b1 = bb[cn + 1];
#pragma unroll
            for (int i = 0; i < 4; i++) {
                const int r0 = wm + i * 16 + qid;
                const int r1 = r0 + 8;
                float2 v0, v1;
                v0.x = acc[i][j][0] + b0; v0.y = acc[i][j][1] + b1;
                v1.x = acc[i][j][2] + b0; v1.y = acc[i][j][3] + b1;
                if (m0 + r0 < n_e) *(float2*)(Cb + (size_t)r0 * NTOT + cn) = v0;
                if (m0 + r1 < n_e) *(float2*)(Cb + (size_t)r1 * NTOT + cn) = v1;
            }
        }
    }
}

// ---------------- combine: out[t] = w0*y[pos0] + w1*y[pos1] ------------------
__global__ void combine_kernel(float* __restrict__ out) {
    const int i = blockIdx.x * blockDim.x + threadIdx.x;
    const int t  = i >> 7;
    const int d4 = i & 127;
    const float w0  = g_wt[2 * t];
    const float w1v = g_wt[2 * t + 1];
    const int p0 = g_pos[2 * t];
    const int p1 = g_pos[2 * t + 1];
    const float4* __restrict__ y4 = (const float4*)g_y;
    const float4 a = y4[(size_t)p0 * 128 + d4];
    const float4 b = y4[(size_t)p1 * 128 + d4];
    float4 r;
    r.x = w0 * a.x + w1v * b.x;
    r.y = w0 * a.y + w1v * b.y;
    r.z = w0 * a.z + w1v * b.z;
    r.w = w0 * a.w + w1v * b.w;
    ((float4*)out)[i] = r;
}

// ---------------- launch -----------------------------------------------------
#define SMEM_BYTES ((2u * BUFA32 + 2u * BUFB32) * 4u)   // 71680 B

extern "C" void kernel_launch(void* const* d_in, const int* in_sizes, int n_in,
                              void* d_out, int out_size) {
    const float* x   = (const float*)d_in[0];
    const float* rw  = (const float*)d_in[1];
    const float* rb  = (const float*)d_in[2];
    const float* w1  = (const float*)d_in[3];
    const float* b1  = (const float*)d_in[4];
    const float* w2  = (const float*)d_in[5];
    const float* b2  = (const float*)d_in[6];
    float* out = (float*)d_out;

    cudaFuncSetAttribute(moe_gemm_kernel<0>,
                         cudaFuncAttributeMaxDynamicSharedMemorySize, SMEM_BYTES);
    cudaFuncSetAttribute(moe_gemm_kernel<1>,
                         cudaFuncAttributeMaxDynamicSharedMemorySize, SMEM_BYTES);

    zero_cnt_kernel<<<1, 32>>>();
    router_kernel<<<NT / 8, 256>>>(x, rw, rb);
    pack_kernel<<<NT * 2, 128>>>(x);

    // fp32 -> fp16 weight converts (natural layout, no transpose)
    conv_kernel<0><<<(EE * DD * FF / 4) / 256, 256>>>(w1);
    conv_kernel<1><<<(EE * FF * DD / 4) / 256, 256>>>(w2);

    // GEMM1: hidden = relu(xg @ w1 + b1)   (K = DD, N = FF)
    moe_gemm_kernel<0><<<dim3(FF / 128, MAXTOK / 128, EE), 256, SMEM_BYTES>>>(b1);
    // GEMM2: y = hidden @ w2 + b2          (K = FF, N = DD)
    moe_gemm_kernel<1><<<dim3(DD / 128, MAXTOK / 128, EE), 256, SMEM_BYTES>>>(b2);

    combine_kernel<<<(NT * DD / 4) / 256, 256>>>(out);
}